// round 3
// baseline (speedup 1.0000x reference)
#include <cuda_runtime.h>
#include <cuda_fp16.h>

// B=512, L=1000, H=128. 2-layer LSTM + linear head.
// 128 persistent CTAs x 512 threads; CTA owns 4 batches for all t.
// Split-k matmul layout: lane l -> kg=l&7 (16-k slice), rg=l>>3 (row group).
// Warp wp owns gate rows wp*32..wp*32+31 (8 per lane, 2 passes of 4).
// Each lane accumulates for ALL 4 batches; kg partials combined by shfl_xor.
// w_hh1: smem (prep-blocked fp16). w_ih2/w_hh2: streamed from L2 (blocked fp16).
// Inner product: fma.rn.f32x2 with fp32 accumulators.

typedef unsigned long long u64;

__device__ uint4 g_pw1[8192];   // w_hh1 blocked fp16
__device__ uint4 g_pw2a[8192];  // w_ih2 blocked fp16
__device__ uint4 g_pw2b[8192];  // w_hh2 blocked fp16
__device__ float g_b1[512];     // b_ih1 + b_hh1
__device__ float g_b2[512];     // b_ih2 + b_hh2

__device__ __forceinline__ u64 pk(float lo, float hi) {
    u64 r; asm("mov.b64 %0,{%1,%2};" : "=l"(r) : "f"(lo), "f"(hi)); return r;
}
__device__ __forceinline__ void fma2(u64& d, u64 a, u64 b) {
    asm("fma.rn.f32x2 %0,%1,%2,%0;" : "+l"(d) : "l"(a), "l"(b));
}
__device__ __forceinline__ float f2sum(u64 a) {
    float lo, hi; asm("mov.b64 {%0,%1}, %2;" : "=f"(lo), "=f"(hi) : "l"(a)); return lo + hi;
}
__device__ __forceinline__ float sigf(float v) {
    return __fdividef(1.f, 1.f + __expf(-v));
}
__device__ __forceinline__ float tanh_f(float v) {
    return 2.f * __fdividef(1.f, 1.f + __expf(-2.f * v)) - 1.f;
}
__device__ __forceinline__ void cvtw(uint4 v, u64& w0, u64& w1, u64& w2, u64& w3) {
    float2 f;
    f = __half22float2(*reinterpret_cast<__half2*>(&v.x)); w0 = pk(f.x, f.y);
    f = __half22float2(*reinterpret_cast<__half2*>(&v.y)); w1 = pk(f.x, f.y);
    f = __half22float2(*reinterpret_cast<__half2*>(&v.z)); w2 = pk(f.x, f.y);
    f = __half22float2(*reinterpret_cast<__half2*>(&v.w)); w3 = pk(f.x, f.y);
}

// Blocked weight layout: linear index = (((w*2+p)*4+i)*2+c)*32 + rg*8 + kg
//   row = w*32 + rg*8 + p*4 + i ; k-chunk = kg*16 + c*8 .. +7 (8 fp16 = uint4)
__global__ void prep_kernel(const float* __restrict__ w_hh1,
                            const float* __restrict__ w_ih2,
                            const float* __restrict__ w_hh2,
                            const float* __restrict__ b_ih1,
                            const float* __restrict__ b_hh1,
                            const float* __restrict__ b_ih2,
                            const float* __restrict__ b_hh2) {
    int idx = blockIdx.x * blockDim.x + threadIdx.x;
    if (idx < 512) {
        g_b1[idx] = b_ih1[idx] + b_hh1[idx];
        g_b2[idx] = b_ih2[idx] + b_hh2[idx];
    }
    if (idx < 3 * 8192) {
        int mat = idx >> 13;
        int r = idx & 8191;
        int w = r >> 9, rem = r & 511;
        int p = (rem >> 8) & 1, i = (rem >> 6) & 3, c = (rem >> 5) & 1, lane = rem & 31;
        int rg = lane >> 3, kg = lane & 7;
        int row = w * 32 + rg * 8 + p * 4 + i;
        int k0 = kg * 16 + c * 8;
        const float* W = (mat == 0) ? w_hh1 : (mat == 1) ? w_ih2 : w_hh2;
        uint4* dst = (mat == 0) ? g_pw1 : (mat == 1) ? g_pw2a : g_pw2b;
        const float* src = W + row * 128 + k0;
        __half2 h01 = __floats2half2_rn(src[0], src[1]);
        __half2 h23 = __floats2half2_rn(src[2], src[3]);
        __half2 h45 = __floats2half2_rn(src[4], src[5]);
        __half2 h67 = __floats2half2_rn(src[6], src[7]);
        uint4 v;
        v.x = *reinterpret_cast<unsigned*>(&h01);
        v.y = *reinterpret_cast<unsigned*>(&h23);
        v.z = *reinterpret_cast<unsigned*>(&h45);
        v.w = *reinterpret_cast<unsigned*>(&h67);
        dst[r] = v;
    }
}

// smem map (bytes):
#define OFF_W1   0        // uint4[8192]          131072
#define OFF_H1   131072   // float[4*160]           2560 (kg-skewed, stride 20/kg)
#define OFF_H2   133632   // float[4*160]           2560
#define OFF_GB   136192   // float[4*516]           8256
#define OFF_XS   144448   // float[1000*4]         16000
#define OFF_PS   160448   // float[16]                64
#define SMEM_TOTAL 160512

__global__ void __launch_bounds__(512, 1)
lstm_main(const float* __restrict__ x, const float* __restrict__ w_ih1,
          const float* __restrict__ w_lin, const float* __restrict__ b_lin,
          float* __restrict__ out) {
    extern __shared__ char smch[];
    uint4* s_w1 = reinterpret_cast<uint4*>(smch + OFF_W1);
    float* h1s = reinterpret_cast<float*>(smch + OFF_H1);
    float* h2s = reinterpret_cast<float*>(smch + OFF_H2);
    float* gb  = reinterpret_cast<float*>(smch + OFF_GB);
    float* xs  = reinterpret_cast<float*>(smch + OFF_XS);
    float* ps  = reinterpret_cast<float*>(smch + OFF_PS);

    const int g = threadIdx.x;
    const int l = g & 31;
    const int wp = g >> 5;
    const int kg = l & 7;
    const int rg = l >> 3;
    const int j = g & 127;       // activation hidden index
    const int ty = g >> 7;       // activation batch index
    const int b0 = blockIdx.x * 4;

    // one-time: blocked w_hh1 -> smem; x transposed -> smem; h zero
    for (int i = g; i < 8192; i += 512) s_w1[i] = g_pw1[i];
    for (int i = g; i < 4000; i += 512) xs[i] = x[(b0 + (i & 3)) * 1000 + (i >> 2)];
    {
        int hoff = ty * 160 + (j >> 4) * 20 + (j & 15);
        h1s[hoff] = 0.f;
        h2s[hoff] = 0.f;
    }

    float c1 = 0.f, c2 = 0.f;
    float b1g0 = g_b1[j],       b1g1 = g_b1[128 + j];
    float b1g2 = g_b1[256 + j], b1g3 = g_b1[384 + j];
    float wg0 = w_ih1[j],       wg1 = w_ih1[128 + j];
    float wg2 = w_ih1[256 + j], wg3 = w_ih1[384 + j];
    float b2g0 = g_b2[j],       b2g1 = g_b2[128 + j];
    float b2g2 = g_b2[256 + j], b2g3 = g_b2[384 + j];
    const float wl = w_lin[j];
    const float bl = b_lin[0];

    const float* h1rd = h1s + kg * 20;   // + b*160 + c*8
    const float* h2rd = h2s + kg * 20;
    float* gwr = gb + wp * 32 + rg * 8;  // + b*516 + p*4

    __syncthreads();

#pragma unroll 1
    for (int t = 0; t < 1000; t++) {
        // ================= layer 1 matmul =================
#pragma unroll
        for (int p = 0; p < 2; p++) {
            u64 acc[16];
#pragma unroll
            for (int q = 0; q < 16; q++) acc[q] = 0ull;
#pragma unroll
            for (int c = 0; c < 2; c++) {
                u64 ha[16];
#pragma unroll
                for (int b = 0; b < 4; b++) {
                    const float* hp = h1rd + b * 160 + c * 8;
                    float4 A = *reinterpret_cast<const float4*>(hp);
                    float4 Bv = *reinterpret_cast<const float4*>(hp + 4);
                    ha[b * 4 + 0] = pk(A.x, A.y);  ha[b * 4 + 1] = pk(A.z, A.w);
                    ha[b * 4 + 2] = pk(Bv.x, Bv.y); ha[b * 4 + 3] = pk(Bv.z, Bv.w);
                }
#pragma unroll
                for (int i = 0; i < 4; i++) {
                    uint4 wv = s_w1[(wp * 16 + p * 8 + i * 2 + c) * 32 + l];
                    u64 w0, w1, w2, w3; cvtw(wv, w0, w1, w2, w3);
#pragma unroll
                    for (int b = 0; b < 4; b++) {
                        fma2(acc[i * 4 + b], w0, ha[b * 4 + 0]);
                        fma2(acc[i * 4 + b], w1, ha[b * 4 + 1]);
                        fma2(acc[i * 4 + b], w2, ha[b * 4 + 2]);
                        fma2(acc[i * 4 + b], w3, ha[b * 4 + 3]);
                    }
                }
            }
            float s[16];
#pragma unroll
            for (int q = 0; q < 16; q++) s[q] = f2sum(acc[q]);
#pragma unroll
            for (int off = 1; off <= 4; off <<= 1)
#pragma unroll
                for (int q = 0; q < 16; q++)
                    s[q] += __shfl_xor_sync(0xffffffffu, s[q], off);
            if (kg == 0) {
#pragma unroll
                for (int b = 0; b < 4; b++)
                    *reinterpret_cast<float4*>(gwr + b * 516 + p * 4) =
                        make_float4(s[b], s[4 + b], s[8 + b], s[12 + b]);
            }
        }
        __syncthreads();

        // ================= layer 1 activation =================
        {
            float xv = xs[t * 4 + ty];
            const float* gB = gb + ty * 516;
            float gi = gB[j]       + b1g0 + wg0 * xv;
            float gf = gB[128 + j] + b1g1 + wg1 * xv;
            float gg = gB[256 + j] + b1g2 + wg2 * xv;
            float go = gB[384 + j] + b1g3 + wg3 * xv;
            float iv = sigf(gi), fv = sigf(gf), gv = tanh_f(gg), ov = sigf(go);
            c1 = fv * c1 + iv * gv;
            h1s[ty * 160 + (j >> 4) * 20 + (j & 15)] = ov * tanh_f(c1);
        }
        __syncthreads();

        // ================= layer 2 matmul =================
#pragma unroll
        for (int p = 0; p < 2; p++) {
            u64 acc[16];
#pragma unroll
            for (int q = 0; q < 16; q++) acc[q] = 0ull;
#pragma unroll
            for (int mat = 0; mat < 2; mat++) {
                const float* hrd = mat ? h2rd : h1rd;
                const uint4* gsrc = mat ? g_pw2b : g_pw2a;
#pragma unroll
                for (int c = 0; c < 2; c++) {
                    u64 ha[16];
#pragma unroll
                    for (int b = 0; b < 4; b++) {
                        const float* hp = hrd + b * 160 + c * 8;
                        float4 A = *reinterpret_cast<const float4*>(hp);
                        float4 Bv = *reinterpret_cast<const float4*>(hp + 4);
                        ha[b * 4 + 0] = pk(A.x, A.y);  ha[b * 4 + 1] = pk(A.z, A.w);
                        ha[b * 4 + 2] = pk(Bv.x, Bv.y); ha[b * 4 + 3] = pk(Bv.z, Bv.w);
                    }
#pragma unroll
                    for (int i = 0; i < 4; i++) {
                        uint4 wv = gsrc[(wp * 16 + p * 8 + i * 2 + c) * 32 + l];
                        u64 w0, w1, w2, w3; cvtw(wv, w0, w1, w2, w3);
#pragma unroll
                        for (int b = 0; b < 4; b++) {
                            fma2(acc[i * 4 + b], w0, ha[b * 4 + 0]);
                            fma2(acc[i * 4 + b], w1, ha[b * 4 + 1]);
                            fma2(acc[i * 4 + b], w2, ha[b * 4 + 2]);
                            fma2(acc[i * 4 + b], w3, ha[b * 4 + 3]);
                        }
                    }
                }
            }
            float s[16];
#pragma unroll
            for (int q = 0; q < 16; q++) s[q] = f2sum(acc[q]);
#pragma unroll
            for (int off = 1; off <= 4; off <<= 1)
#pragma unroll
                for (int q = 0; q < 16; q++)
                    s[q] += __shfl_xor_sync(0xffffffffu, s[q], off);
            if (kg == 0) {
#pragma unroll
                for (int b = 0; b < 4; b++)
                    *reinterpret_cast<float4*>(gwr + b * 516 + p * 4) =
                        make_float4(s[b], s[4 + b], s[8 + b], s[12 + b]);
            }
        }
        __syncthreads();

        // ================= layer 2 activation + head =================
        float h2v;
        {
            const float* gB = gb + ty * 516;
            float gi = gB[j]       + b2g0;
            float gf = gB[128 + j] + b2g1;
            float gg = gB[256 + j] + b2g2;
            float go = gB[384 + j] + b2g3;
            float iv = sigf(gi), fv = sigf(gf), gv = tanh_f(gg), ov = sigf(go);
            c2 = fv * c2 + iv * gv;
            h2v = ov * tanh_f(c2);
            h2s[ty * 160 + (j >> 4) * 20 + (j & 15)] = h2v;
        }
        float pr = wl * h2v;
#pragma unroll
        for (int off = 16; off >= 1; off >>= 1) pr += __shfl_xor_sync(0xffffffffu, pr, off);
        if (l == 0) ps[wp] = pr;
        __syncthreads();
        if (g < 4)
            out[(b0 + g) * 1000 + t] = ps[g * 4] + ps[g * 4 + 1] + ps[g * 4 + 2] + ps[g * 4 + 3] + bl;
    }
}

extern "C" void kernel_launch(void* const* d_in, const int* in_sizes, int n_in,
                              void* d_out, int out_size) {
    const float* x     = (const float*)d_in[0];
    const float* w_ih1 = (const float*)d_in[1];
    const float* w_hh1 = (const float*)d_in[2];
    const float* b_ih1 = (const float*)d_in[3];
    const float* b_hh1 = (const float*)d_in[4];
    const float* w_ih2 = (const float*)d_in[5];
    const float* w_hh2 = (const float*)d_in[6];
    const float* b_ih2 = (const float*)d_in[7];
    const float* b_hh2 = (const float*)d_in[8];
    const float* w_lin = (const float*)d_in[9];
    const float* b_lin = (const float*)d_in[10];
    float* out = (float*)d_out;

    cudaFuncSetAttribute(lstm_main, cudaFuncAttributeMaxDynamicSharedMemorySize, SMEM_TOTAL);

    prep_kernel<<<48, 512>>>(w_hh1, w_ih2, w_hh2, b_ih1, b_hh1, b_ih2, b_hh2);
    lstm_main<<<128, 512, SMEM_TOTAL>>>(x, w_ih1, w_lin, b_lin, out);
}

// round 4
// speedup vs baseline: 5.3774x; 5.3774x over previous
#include <cuda_runtime.h>
#include <cuda_fp16.h>

// B=512, L=1000, H=128. 2-layer LSTM + linear head, via mma.sync tensor cores.
// 64 CTAs x 512 threads; CTA owns 8 batches (N=8 of m16n8k16) for all 1000 steps.
// Warp w: gate rows [32w, 32w+32) = mtiles 2w, 2w+1.
// Weights fp16, pre-swizzled by prep kernel into mma A-fragment order:
//   frag[mt*256 + kt*32 + lane] = uint4 {a0,a1,a2,a3}.
// w_hh1: smem. w_hh2: even mtile resident in regs, odd mtile in smem.
// w_ih2: streamed from L2 (frag order -> coalesced LDG.128).
// h kept in smem in B-fragment layout (written by activation threads as fp16).
// Accumulation fp32 (mma C/D f32); cell state c fp32 in registers.

typedef unsigned long long u64;

__device__ uint4 g_w1f[8192];    // w_hh1 frags
__device__ uint4 g_w2af[8192];   // w_ih2 frags
__device__ uint4 g_w2bf[8192];   // w_hh2 frags
__device__ float g_b1[512];      // b_ih1 + b_hh1
__device__ float g_b2[512];      // b_ih2 + b_hh2

__device__ __forceinline__ void mma16816(float& d0, float& d1, float& d2, float& d3,
                                         uint4 a, uint2 b) {
    asm volatile(
        "mma.sync.aligned.m16n8k16.row.col.f32.f16.f16.f32 "
        "{%0,%1,%2,%3},{%4,%5,%6,%7},{%8,%9},{%0,%1,%2,%3};"
        : "+f"(d0), "+f"(d1), "+f"(d2), "+f"(d3)
        : "r"(a.x), "r"(a.y), "r"(a.z), "r"(a.w), "r"(b.x), "r"(b.y));
}
__device__ __forceinline__ float sigf(float v) {
    return __fdividef(1.f, 1.f + __expf(-v));
}
__device__ __forceinline__ float tanh_f(float v) {
    return 2.f * __fdividef(1.f, 1.f + __expf(-2.f * v)) - 1.f;
}

__global__ void prep_kernel(const float* __restrict__ w_hh1,
                            const float* __restrict__ w_ih2,
                            const float* __restrict__ w_hh2,
                            const float* __restrict__ b_ih1,
                            const float* __restrict__ b_hh1,
                            const float* __restrict__ b_ih2,
                            const float* __restrict__ b_hh2) {
    int idx = blockIdx.x * blockDim.x + threadIdx.x;
    if (idx < 512) {
        g_b1[idx] = b_ih1[idx] + b_hh1[idx];
        g_b2[idx] = b_ih2[idx] + b_hh2[idx];
    }
    if (idx < 3 * 8192) {
        int mat = idx >> 13;
        int r = idx & 8191;
        int mt = r >> 8, kt = (r >> 5) & 7, lane = r & 31;
        int g = lane >> 2, t = lane & 3;
        int m0 = mt * 16 + g, m1 = m0 + 8;
        int k0 = kt * 16 + 2 * t;
        const float* W = (mat == 0) ? w_hh1 : (mat == 1) ? w_ih2 : w_hh2;
        uint4* dst = (mat == 0) ? g_w1f : (mat == 1) ? g_w2af : g_w2bf;
        __half2 p;
        uint4 v;
        p = __floats2half2_rn(W[m0 * 128 + k0],     W[m0 * 128 + k0 + 1]); v.x = *(unsigned*)&p;
        p = __floats2half2_rn(W[m1 * 128 + k0],     W[m1 * 128 + k0 + 1]); v.y = *(unsigned*)&p;
        p = __floats2half2_rn(W[m0 * 128 + k0 + 8], W[m0 * 128 + k0 + 9]); v.z = *(unsigned*)&p;
        p = __floats2half2_rn(W[m1 * 128 + k0 + 8], W[m1 * 128 + k0 + 9]); v.w = *(unsigned*)&p;
        dst[r] = v;
    }
}

// smem map (bytes)
#define OFF_W1    0        // uint4[8192]  w_hh1 frags          131072
#define OFF_W2B   131072   // uint4[4096]  w_hh2 odd-mtile frags 65536
#define OFF_GS    196608   // float[512*9] gate buffer           18432
#define OFF_H1F   215040   // half[1024]   h1 B-frag layout       2048
#define OFF_H2F   217088   // half[1024]   h2 B-frag layout       2048
#define OFF_PS    219136   // float[32]    head partials           128
#define SMEM_TOTAL 219264

__global__ void __launch_bounds__(512, 1)
lstm_main(const float* __restrict__ x, const float* __restrict__ w_ih1,
          const float* __restrict__ w_lin, const float* __restrict__ b_lin,
          float* __restrict__ out) {
    extern __shared__ char smch[];
    uint4* sw1   = reinterpret_cast<uint4*>(smch + OFF_W1);
    uint4* sw2b  = reinterpret_cast<uint4*>(smch + OFF_W2B);
    float* gs    = reinterpret_cast<float*>(smch + OFF_GS);
    uint2* h1fp  = reinterpret_cast<uint2*>(smch + OFF_H1F);
    uint2* h2fp  = reinterpret_cast<uint2*>(smch + OFF_H2F);
    __half* h1h  = reinterpret_cast<__half*>(smch + OFF_H1F);
    __half* h2h  = reinterpret_cast<__half*>(smch + OFF_H2F);
    float* ps    = reinterpret_cast<float*>(smch + OFF_PS);

    const int tid = threadIdx.x;
    const int lane = tid & 31;
    const int wp = tid >> 5;
    const int j = tid & 127;    // activation: hidden index
    const int bq = tid >> 7;    // activation: batch quarter (handles b=bq, b=bq+4)
    const int b0c = blockIdx.x * 8;

    // ---- one-time smem fills ----
    for (int i = tid; i < 8192; i += 512) sw1[i] = g_w1f[i];
    for (int i = tid; i < 4096; i += 512) {
        int w2 = i >> 8, kt = (i >> 5) & 7, ln = i & 31;
        sw2b[i] = g_w2bf[(2 * w2 + 1) * 256 + kt * 32 + ln];
    }
    for (int i = tid; i < 1024; i += 512)
        reinterpret_cast<unsigned*>(smch + OFF_H1F)[i] = 0;  // zeros h1f + h2f

    // resident w_hh2 even-mtile fragments
    uint4 rw[8];
#pragma unroll
    for (int kt = 0; kt < 8; kt++) rw[kt] = g_w2bf[(2 * wp) * 256 + kt * 32 + lane];

    // activation-role constants
    const float b10 = g_b1[j],       b11 = g_b1[128 + j];
    const float b12 = g_b1[256 + j], b13 = g_b1[384 + j];
    const float wg0 = w_ih1[j],       wg1 = w_ih1[128 + j];
    const float wg2 = w_ih1[256 + j], wg3 = w_ih1[384 + j];
    const float b20 = g_b2[j],       b21 = g_b2[128 + j];
    const float b22 = g_b2[256 + j], b23 = g_b2[384 + j];
    const float wl = w_lin[j];
    const float bl = b_lin[0];
    float c1a = 0.f, c1b = 0.f, c2a = 0.f, c2b = 0.f;
    float xn0 = x[(b0c + bq) * 1000];
    float xn1 = x[(b0c + bq + 4) * 1000];

    // h B-fragment store offsets for this activation thread (constant over t)
    const int hkt = j >> 4, hkk = j & 15;
    const int hreg = hkk >> 3, htt = (hkk >> 1) & 3, hhalf = hkk & 1;
    const int hoffA = ((hkt * 32 + (bq * 4 + htt)) * 2 + hreg) * 2 + hhalf;
    const int hoffB = ((hkt * 32 + ((bq + 4) * 4 + htt)) * 2 + hreg) * 2 + hhalf;

    // matmul-role constants
    const int fi0 = (2 * wp) * 256 + lane;      // + kt*32
    const int fi1 = (2 * wp + 1) * 256 + lane;
    const int dg = lane >> 2, dt2 = (lane & 3) * 2;
    const int ra = 2 * wp * 16 + dg;            // D rows: ra, ra+8, ra+16, ra+24
    const int ja = j * 9 + bq;                  // activation gate-read base

    __syncthreads();

#pragma unroll 1
    for (int t = 0; t < 1000; t++) {
        // ================= MM1: gates1 = w_hh1 . h1  =================
        uint4 bufA[8];
#pragma unroll
        for (int kt = 0; kt < 8; kt++) bufA[kt] = g_w2af[fi0 + kt * 32];  // prefetch w_ih2 mt0

        float d00 = 0.f, d01 = 0.f, d02 = 0.f, d03 = 0.f;
        float d10 = 0.f, d11 = 0.f, d12 = 0.f, d13 = 0.f;
#pragma unroll
        for (int kt = 0; kt < 8; kt++) {
            uint2 B = h1fp[kt * 32 + lane];
            mma16816(d00, d01, d02, d03, sw1[fi0 + kt * 32], B);
            mma16816(d10, d11, d12, d13, sw1[fi1 + kt * 32], B);
        }
        gs[ra * 9 + dt2] = d00;        gs[ra * 9 + dt2 + 1] = d01;
        gs[(ra + 8) * 9 + dt2] = d02;  gs[(ra + 8) * 9 + dt2 + 1] = d03;
        gs[(ra + 16) * 9 + dt2] = d10; gs[(ra + 16) * 9 + dt2 + 1] = d11;
        gs[(ra + 24) * 9 + dt2] = d12; gs[(ra + 24) * 9 + dt2 + 1] = d13;
        __syncthreads();

        // ================= ACT1 =================
        {
            float xa = xn0, xb = xn1;
            if (t < 999) {
                xn0 = x[(b0c + bq) * 1000 + t + 1];
                xn1 = x[(b0c + bq + 4) * 1000 + t + 1];
            }
            float gia = gs[ja] + b10 + wg0 * xa;
            float gfa = gs[ja + 1152] + b11 + wg1 * xa;
            float gga = gs[ja + 2304] + b12 + wg2 * xa;
            float goa = gs[ja + 3456] + b13 + wg3 * xa;
            float gib = gs[ja + 4] + b10 + wg0 * xb;
            float gfb = gs[ja + 1156] + b11 + wg1 * xb;
            float ggb = gs[ja + 2308] + b12 + wg2 * xb;
            float gob = gs[ja + 3460] + b13 + wg3 * xb;
            c1a = sigf(gfa) * c1a + sigf(gia) * tanh_f(gga);
            c1b = sigf(gfb) * c1b + sigf(gib) * tanh_f(ggb);
            float h1a = sigf(goa) * tanh_f(c1a);
            float h1b = sigf(gob) * tanh_f(c1b);
            h1h[hoffA] = __float2half_rn(h1a);
            h1h[hoffB] = __float2half_rn(h1b);
        }
        __syncthreads();

        // ================= MM2: gates2 = w_ih2 . h1 + w_hh2 . h2 =================
        d00 = 0.f; d01 = 0.f; d02 = 0.f; d03 = 0.f;
        d10 = 0.f; d11 = 0.f; d12 = 0.f; d13 = 0.f;
#pragma unroll
        for (int kt = 0; kt < 8; kt++) {          // w_ih2 mt0 (buffered), refill with mt1
            uint2 B = h1fp[kt * 32 + lane];
            mma16816(d00, d01, d02, d03, bufA[kt], B);
            bufA[kt] = g_w2af[fi1 + kt * 32];
        }
#pragma unroll
        for (int kt = 0; kt < 8; kt++) {          // w_hh2 mt0 (resident regs)
            uint2 B = h2fp[kt * 32 + lane];
            mma16816(d00, d01, d02, d03, rw[kt], B);
        }
#pragma unroll
        for (int kt = 0; kt < 8; kt++) {          // w_hh2 mt1 (smem)
            uint2 B = h2fp[kt * 32 + lane];
            mma16816(d10, d11, d12, d13, sw2b[wp * 256 + kt * 32 + lane], B);
        }
#pragma unroll
        for (int kt = 0; kt < 8; kt++) {          // w_ih2 mt1 (buffered)
            uint2 B = h1fp[kt * 32 + lane];
            mma16816(d10, d11, d12, d13, bufA[kt], B);
        }
        gs[ra * 9 + dt2] = d00;        gs[ra * 9 + dt2 + 1] = d01;
        gs[(ra + 8) * 9 + dt2] = d02;  gs[(ra + 8) * 9 + dt2 + 1] = d03;
        gs[(ra + 16) * 9 + dt2] = d10; gs[(ra + 16) * 9 + dt2 + 1] = d11;
        gs[(ra + 24) * 9 + dt2] = d12; gs[(ra + 24) * 9 + dt2 + 1] = d13;
        __syncthreads();

        // ================= ACT2 + head =================
        {
            float gia = gs[ja] + b20;
            float gfa = gs[ja + 1152] + b21;
            float gga = gs[ja + 2304] + b22;
            float goa = gs[ja + 3456] + b23;
            float gib = gs[ja + 4] + b20;
            float gfb = gs[ja + 1156] + b21;
            float ggb = gs[ja + 2308] + b22;
            float gob = gs[ja + 3460] + b23;
            c2a = sigf(gfa) * c2a + sigf(gia) * tanh_f(gga);
            c2b = sigf(gfb) * c2b + sigf(gib) * tanh_f(ggb);
            float h2a = sigf(goa) * tanh_f(c2a);
            float h2b = sigf(gob) * tanh_f(c2b);
            h2h[hoffA] = __float2half_rn(h2a);
            h2h[hoffB] = __float2half_rn(h2b);
            float p0 = wl * h2a, p1 = wl * h2b;
#pragma unroll
            for (int off = 16; off >= 1; off >>= 1) {
                p0 += __shfl_xor_sync(0xffffffffu, p0, off);
                p1 += __shfl_xor_sync(0xffffffffu, p1, off);
            }
            if (lane == 0) { ps[wp * 2] = p0; ps[wp * 2 + 1] = p1; }
        }
        __syncthreads();
        if (tid < 8) {
            int b = tid;
            float s;
            if (b < 4)
                s = ps[b * 8] + ps[b * 8 + 2] + ps[b * 8 + 4] + ps[b * 8 + 6];
            else {
                int q = b - 4;
                s = ps[q * 8 + 1] + ps[q * 8 + 3] + ps[q * 8 + 5] + ps[q * 8 + 7];
            }
            out[(b0c + b) * 1000 + t] = s + bl;
        }
    }
}

extern "C" void kernel_launch(void* const* d_in, const int* in_sizes, int n_in,
                              void* d_out, int out_size) {
    const float* x     = (const float*)d_in[0];
    const float* w_ih1 = (const float*)d_in[1];
    const float* w_hh1 = (const float*)d_in[2];
    const float* b_ih1 = (const float*)d_in[3];
    const float* b_hh1 = (const float*)d_in[4];
    const float* w_ih2 = (const float*)d_in[5];
    const float* w_hh2 = (const float*)d_in[6];
    const float* b_ih2 = (const float*)d_in[7];
    const float* b_hh2 = (const float*)d_in[8];
    const float* w_lin = (const float*)d_in[9];
    const float* b_lin = (const float*)d_in[10];
    float* out = (float*)d_out;

    cudaFuncSetAttribute(lstm_main, cudaFuncAttributeMaxDynamicSharedMemorySize, SMEM_TOTAL);

    prep_kernel<<<48, 512>>>(w_hh1, w_ih2, w_hh2, b_ih1, b_hh1, b_ih2, b_hh2);
    lstm_main<<<64, 512, SMEM_TOTAL>>>(x, w_ih1, w_lin, b_lin, out);
}